// round 2
// baseline (speedup 1.0000x reference)
#include <cuda_runtime.h>

#define INV_SQRT2 0.70710678118654752440f

// Inter-level lowpass scratch, planar layout: [tree][b][c][H][W]
__device__ float g_lo1[4 * 8 * 3 * 256 * 256];  // after level 1 (256x256)
__device__ float g_lo2[4 * 8 * 3 * 128 * 128];  // after level 2 (128x128)
__constant__ float c_filt[80];  // [0..39] Faf, [40..79] af; layout [m/n][lo,hi][10]

// Column (horizontal) conv for one tree at one (i, jp) task: produces
// ll/lh/hl/hh for output columns j=2jp and 2jp+1.
template <int TI, int PC>
__device__ __forceinline__ void tree_conv(
    const float* __restrict__ s_row, int foff, int rr, int n, int i, int jp,
    float v[4][2])
{
    const float* Rlo = s_row + ((rr * 2 + 0) * TI + i) * PC + 4 * jp;
    const float* Rhi = s_row + ((rr * 2 + 1) * TI + i) * PC + 4 * jp;
    float rl[12], rh[12];
#pragma unroll
    for (int q = 0; q < 3; q++) {
        float4 a = *(const float4*)(Rlo + 4 * q);
        rl[4*q+0] = a.x; rl[4*q+1] = a.y; rl[4*q+2] = a.z; rl[4*q+3] = a.w;
        float4 bq = *(const float4*)(Rhi + 4 * q);
        rh[4*q+0] = bq.x; rh[4*q+1] = bq.y; rh[4*q+2] = bq.z; rh[4*q+3] = bq.w;
    }
    float flo[10], fhi[10];
#pragma unroll
    for (int u = 0; u < 10; u++) {
        flo[u] = c_filt[foff + (n * 2 + 0) * 10 + 9 - u];
        fhi[u] = c_filt[foff + (n * 2 + 1) * 10 + 9 - u];
    }
#pragma unroll
    for (int p = 0; p < 2; p++) {
        float ll = 0.f, lh = 0.f, hl = 0.f, hh = 0.f;
#pragma unroll
        for (int u = 0; u < 10; u++) {
            float a = rl[2 * p + u], bb = rh[2 * p + u];
            ll += flo[u] * a;  lh += fhi[u] * a;
            hl += flo[u] * bb; hh += fhi[u] * bb;
        }
        v[0][p] = ll; v[1][p] = lh; v[2][p] = hl; v[3][p] = hh;
    }
}

// Fused 2D analysis filter bank for one level, all 4 dual trees.
//   out[n] = sum_s f[s] * x[(2n - s + 5) mod N]   (per axis, circular)
template <int TI, int TJ, bool SHARED>
__global__ __launch_bounds__(256, 3) void afb_kernel(
    const float* __restrict__ in_base,
    int tree_stride, int Hin, int foff, float scale, int levelj,
    float* __restrict__ lo_out, float* __restrict__ out)
{
    const int Win = Hin, Hout = Hin >> 1, Wout = Hout;
    constexpr int PR = 2 * TI + 8;
    constexpr int PC = 2 * TJ + 8;
    constexpr int NSLOT = SHARED ? 1 : 4;
    constexpr int NR    = SHARED ? 2 : 4;
    constexpr int PC4   = PC / 4;
    constexpr int JP    = TJ / 2;

    extern __shared__ float smem[];
    float* s_in  = smem;                    // NSLOT * PR * PC
    float* s_row = smem + NSLOT * PR * PC;  // NR * 2 * TI * PC

    const int tid = threadIdx.x;
    const int b = blockIdx.z, c = blockIdx.y;
    const int tilesW = Wout / TJ;
    const int i0 = (blockIdx.x / tilesW) * TI;
    const int j0 = (blockIdx.x % tilesW) * TJ;

    // ---- Load input patch(es), circular indexing (all 32-bit) ----
    const int g0r = 2 * i0 - 4, g0c = 2 * j0 - 4;
    const float* inp = SHARED ? (in_base + (b * Hin * Win) * 3 + c)
                              : (in_base + ((b * 3 + c) * Hin) * Win);
    for (int idx = tid; idx < NSLOT * PR * PC; idx += 256) {
        int slot = idx / (PR * PC);
        int rem  = idx % (PR * PC);
        int pr = rem / PC, pc = rem % PC;
        int h = g0r + pr; if (h < 0) h += Hin; if (h >= Hin) h -= Hin;
        int w = g0c + pc; if (w < 0) w += Win; if (w >= Win) w -= Win;
        float v;
        if (SHARED) v = inp[(h * Win + w) * 3];
        else        v = inp[slot * tree_stride + h * Win + w];
        s_in[idx] = v * scale;
    }
    __syncthreads();

    // ---- Row (vertical) pass: float4 over pc ----
#pragma unroll
    for (int r = 0; r < NR; r++) {
        const int m    = SHARED ? r : (r >> 1);
        const int slot = SHARED ? 0 : r;
#pragma unroll
        for (int lh = 0; lh < 2; lh++) {
            float fr[10];
#pragma unroll
            for (int u = 0; u < 10; u++)
                fr[u] = c_filt[foff + (m * 2 + lh) * 10 + 9 - u];
            for (int task = tid; task < TI * PC4; task += 256) {
                int i   = task / PC4;
                int pc4 = (task - i * PC4) * 4;
                const float* pin = s_in + slot * (PR * PC) + (2 * i) * PC + pc4;
                float4 acc = make_float4(0.f, 0.f, 0.f, 0.f);
#pragma unroll
                for (int u = 0; u < 10; u++) {
                    float4 xv = *(const float4*)(pin + u * PC);
                    acc.x += fr[u] * xv.x; acc.y += fr[u] * xv.y;
                    acc.z += fr[u] * xv.z; acc.w += fr[u] * xv.w;
                }
                *(float4*)(s_row + ((r * 2 + lh) * TI + i) * PC + pc4) = acc;
            }
        }
    }
    __syncthreads();

    // ---- Col pass (2 output columns / task) + dual-tree combine + scatter ----
    const int S = 256 >> levelj;
    for (int task = tid; task < TI * JP; task += 256) {
        const int i  = task / JP;      // JP is a power of two
        const int jp = task % JP;
        const int oi  = i0 + i;
        const int oj0 = j0 + 2 * jp;

        // pairs: (t0,t3) -> sum tile(0,0), diff tile(1,1)
        //        (t1,t2) -> sum tile(0,1), diff tile(1,0)
#pragma unroll
        for (int pr2 = 0; pr2 < 2; pr2++) {
            const int ta = pr2 == 0 ? 0 : 1;
            const int tb = pr2 == 0 ? 3 : 2;
            const int nS = pr2;          // sum tile (0, pr2)
            const int nD = 1 - pr2;      // diff tile (1, 1-pr2)

            float va[4][2], vb[4][2];
            tree_conv<TI, PC>(s_row, foff, SHARED ? (ta >> 1) : ta, ta & 1, i, jp, va);
            tree_conv<TI, PC>(s_row, foff, SHARED ? (tb >> 1) : tb, tb & 1, i, jp, vb);

            // Lowpass
            if (lo_out) {
                int ia = ((ta * 8 + b) * 3 + c) * (Hout * Wout) + oi * Wout + oj0;
                lo_out[ia]     = va[0][0];
                lo_out[ia + 1] = va[0][1];
                int ib = ((tb * 8 + b) * 3 + c) * (Hout * Wout) + oi * Wout + oj0;
                lo_out[ib]     = vb[0][0];
                lo_out[ib + 1] = vb[0][1];
            } else {
                // final level: raw lowpass at tile(m,n), offset (0,0)
                int ma = ta >> 1, na = ta & 1;
                int mb = tb >> 1, nb = tb & 1;
#pragma unroll
                for (int p = 0; p < 2; p++) {
                    out[((b * 1024 + ma * 512 + oi) * 1024 + na * 512 + oj0 + p) * 3 + c] = va[0][p];
                    out[((b * 1024 + mb * 512 + oi) * 1024 + nb * 512 + oj0 + p) * 3 + c] = vb[0][p];
                }
            }
            // Subbands: s0=LH @(0,S), s1=HL @(S,0), s2=HH @(S,S)
#pragma unroll
            for (int s = 0; s < 3; s++) {
                const int ro = (s == 0) ? 0 : S;
                const int co = (s == 1) ? 0 : S;
#pragma unroll
                for (int p = 0; p < 2; p++) {
                    float sum = (va[s + 1][p] + vb[s + 1][p]) * INV_SQRT2;
                    float dif = (va[s + 1][p] - vb[s + 1][p]) * INV_SQRT2;
                    int r = ro + oi, cc = co + oj0 + p;
                    out[((b * 1024 + r) * 1024 + nS * 512 + cc) * 3 + c] = sum;            // tile (0,nS)
                    out[((b * 1024 + 512 + r) * 1024 + nD * 512 + cc) * 3 + c] = dif;      // tile (1,nD)
                }
            }
        }
    }
}

extern "C" void kernel_launch(void* const* d_in, const int* in_sizes, int n_in,
                              void* d_out, int out_size)
{
    const float* x   = (const float*)d_in[0];
    const float* Faf = (const float*)d_in[1];
    const float* af  = (const float*)d_in[2];
    float* out = (float*)d_out;

    float *lo1, *lo2;
    cudaGetSymbolAddress((void**)&lo1, g_lo1);
    cudaGetSymbolAddress((void**)&lo2, g_lo2);

    cudaMemcpyToSymbolAsync(c_filt, Faf, 40 * sizeof(float), 0,
                            cudaMemcpyDeviceToDevice);
    cudaMemcpyToSymbolAsync(c_filt, af, 40 * sizeof(float), 40 * sizeof(float),
                            cudaMemcpyDeviceToDevice);

    // Level 1: in x (512, NHWC shared), out subbands (256) + lo1
    {
        dim3 grid((256 / 16) * (256 / 32), 3, 8);   // 3072 CTAs
        size_t smem = (1 * 40 * 72 + 2 * 2 * 16 * 72) * sizeof(float); // 29952 B
        afb_kernel<16, 32, true><<<grid, 256, smem>>>(
            x, 0, 512, 0, 0.5f, 0, lo1, out);
    }
    // Level 2: in lo1 (256, planar per-tree), out subbands (128) + lo2
    {
        dim3 grid((128 / 16) * (128 / 16), 3, 8);   // 1536 CTAs
        size_t smem = (4 * 40 * 40 + 4 * 2 * 16 * 40) * sizeof(float); // 46080 B
        afb_kernel<16, 16, false><<<grid, 256, smem>>>(
            lo1, 8 * 3 * 256 * 256, 256, 40, 1.0f, 1, lo2, out);
    }
    // Level 3: in lo2 (128), out subbands (64) + raw lowpass into out
    {
        dim3 grid((64 / 8) * (64 / 16), 3, 8);      // 768 CTAs
        size_t smem = (4 * 24 * 40 + 4 * 2 * 8 * 40) * sizeof(float); // 25600 B
        afb_kernel<8, 16, false><<<grid, 256, smem>>>(
            lo2, 8 * 3 * 128 * 128, 128, 40, 1.0f, 2, nullptr, out);
    }
}

// round 3
// speedup vs baseline: 1.2658x; 1.2658x over previous
#include <cuda_runtime.h>

#define INV_SQRT2 0.70710678118654752440f

typedef unsigned long long u64;

// Inter-level lowpass scratch, layout [tree][b][h][w][c] (c fastest)
__device__ float g_lo1[4 * 8 * 256 * 256 * 3];
__device__ float g_lo2[4 * 8 * 128 * 128 * 3];
__constant__ float c_filt[80];  // [0..39] Faf, [40..79] af; [m/n][lo,hi][10]

__device__ __forceinline__ u64 pk(float lo, float hi) {
    u64 r; asm("mov.b64 %0,{%1,%2};" : "=l"(r) : "f"(lo), "f"(hi)); return r;
}
__device__ __forceinline__ void unpk(u64 v, float& lo, float& hi) {
    asm("mov.b64 {%0,%1},%2;" : "=f"(lo), "=f"(hi) : "l"(v));
}
__device__ __forceinline__ u64 fma2(u64 a, u64 b, u64 c) {
    u64 d; asm("fma.rn.f32x2 %0,%1,%2,%3;" : "=l"(d) : "l"(a), "l"(b), "l"(c)); return d;
}

// =============================== Level 1 ===================================
// Input x: NHWC (8,512,512,3). 2 shared row-trees, 4 output trees, 3 ch/block.
template <int TI, int TJ>
__global__ __launch_bounds__(256, 4) void afb_l1(
    const float* __restrict__ x, float* __restrict__ lo1, float* __restrict__ out)
{
    constexpr int PR = 2 * TI + 8, PC = 2 * TJ + 8;
    constexpr int CS = PR * PC + 8;          // per-channel stride in s_in
    extern __shared__ float sm[];
    float* s_in = sm;                        // 3*CS floats
    u64* s_row = (u64*)(sm + 3 * CS);        // [m][i][pc][c] packed (lo,hi)

    const int tid = threadIdx.x;
    const int b = blockIdx.y;
    constexpr int TW = 256 / TJ;
    const int i0 = (blockIdx.x / TW) * TI, j0 = (blockIdx.x % TW) * TJ;
    const int g0r = 2 * i0 - 4, g0c = 2 * j0 - 4;
    const float* xb = x + b * (512 * 512 * 3);

    // ---- Load (coalesced over (w,c)) ----
    for (int idx = tid; idx < PR * PC * 3; idx += 256) {
        int pr = idx / (PC * 3);
        int rem = idx - pr * (PC * 3);
        int pc = rem / 3, c = rem - pc * 3;
        int h = g0r + pr; if (h < 0) h += 512; if (h >= 512) h -= 512;
        int w = g0c + pc; if (w < 0) w += 512; if (w >= 512) w -= 512;
        s_in[c * CS + pr * PC + pc] = xb[(h * 512 + w) * 3 + c] * 0.5f;
    }
    __syncthreads();

    // ---- Row pass: packed (lo,hi) per (m,i,pc,c) ----
#pragma unroll
    for (int m = 0; m < 2; m++) {
        u64 f2[10];
#pragma unroll
        for (int u = 0; u < 10; u++)
            f2[u] = pk(c_filt[(m * 2 + 0) * 10 + 9 - u],
                       c_filt[(m * 2 + 1) * 10 + 9 - u]);
        for (int idx = tid; idx < TI * 3 * PC; idx += 256) {
            int pc = idx % PC;
            int t = idx / PC;
            int c = t % 3, i = t / 3;
            const float* pin = s_in + c * CS + (2 * i) * PC + pc;
            u64 acc = 0;
#pragma unroll
            for (int u = 0; u < 10; u++) {
                float xv = pin[u * PC];
                acc = fma2(pk(xv, xv), f2[u], acc);
            }
            s_row[((m * TI + i) * PC + pc) * 3 + c] = acc;
        }
    }
    __syncthreads();

    // ---- Col pass + combine + coalesced scatter ----
    for (int idx = tid; idx < TI * TJ * 3; idx += 256) {
        int c = idx % 3;
        int t = idx / 3;
        int j = t % TJ, i = t / TJ;
        float ll[4], vs[3][4];   // vs[0]=lh, vs[1]=hl, vs[2]=hh
#pragma unroll
        for (int m = 0; m < 2; m++) {
            const u64* R = s_row + ((m * TI + i) * PC + 2 * j) * 3 + c;
            u64 A0 = 0, B0 = 0, A1 = 0, B1 = 0;
#pragma unroll
            for (int u = 0; u < 10; u++) {
                u64 wv = R[u * 3];
                float l0 = c_filt[0 * 10 + 9 - u], h0 = c_filt[1 * 10 + 9 - u];
                float l1 = c_filt[2 * 10 + 9 - u], h1 = c_filt[3 * 10 + 9 - u];
                A0 = fma2(pk(l0, l0), wv, A0);
                B0 = fma2(pk(h0, h0), wv, B0);
                A1 = fma2(pk(l1, l1), wv, A1);
                B1 = fma2(pk(h1, h1), wv, B1);
            }
            int t0 = m * 2, t1 = m * 2 + 1;
            unpk(A0, ll[t0], vs[1][t0]); unpk(B0, vs[0][t0], vs[2][t0]);
            unpk(A1, ll[t1], vs[1][t1]); unpk(B1, vs[0][t1], vs[2][t1]);
        }
        const int oi = i0 + i, oj = j0 + j;
#pragma unroll
        for (int tr = 0; tr < 4; tr++)
            lo1[((tr * 8 + b) * 65536 + oi * 256 + oj) * 3 + c] = ll[tr];
        float* ob = out + b * (1024 * 1024 * 3);
#pragma unroll
        for (int s = 0; s < 3; s++) {
            const int ro = (s == 0) ? 0 : 256;
            const int co = (s == 1) ? 0 : 256;
            float p00 = (vs[s][0] + vs[s][3]) * INV_SQRT2;
            float p11 = (vs[s][0] - vs[s][3]) * INV_SQRT2;
            float p01 = (vs[s][1] + vs[s][2]) * INV_SQRT2;
            float p10 = (vs[s][1] - vs[s][2]) * INV_SQRT2;
            int r = ro + oi, cc = co + oj;
            ob[(r * 1024 + cc) * 3 + c]               = p00;
            ob[(r * 1024 + 512 + cc) * 3 + c]         = p01;
            ob[((512 + r) * 1024 + cc) * 3 + c]       = p10;
            ob[((512 + r) * 1024 + 512 + cc) * 3 + c] = p11;
        }
    }
}

// ============================ Levels 2 and 3 ===============================
// Pair-per-block: blockIdx.y = p. slot0 tree = p, slot1 tree = 3-p.
// Row-tree m == slot; col-tree n == slot ^ p.
template <int TI, int TJ, int Hin, int SBS, bool FINAL>
__global__ __launch_bounds__(256, 4) void afb_l23(
    const float* __restrict__ lo_in, float* __restrict__ lo_out,
    float* __restrict__ out)
{
    constexpr int PR = 2 * TI + 8, PC = 2 * TJ + 8;
    constexpr int CS = PR * PC + 8;
    constexpr int Hout = Hin / 2;
    extern __shared__ float sm[];
    float* s_in = sm;                        // [slot][c][PR][PC] = 6*CS
    u64* s_row = (u64*)(sm + 6 * CS);        // [slot][i][pc][c]

    const int tid = threadIdx.x;
    const int p = blockIdx.y, b = blockIdx.z;
    constexpr int TW = Hout / TJ;
    const int i0 = (blockIdx.x / TW) * TI, j0 = (blockIdx.x % TW) * TJ;
    const int g0r = 2 * i0 - 4, g0c = 2 * j0 - 4;

    // ---- Load both trees (coalesced) ----
#pragma unroll
    for (int slot = 0; slot < 2; slot++) {
        const int tr = slot == 0 ? p : 3 - p;
        const float* ib = lo_in + (tr * 8 + b) * (Hin * Hin * 3);
        for (int idx = tid; idx < PR * PC * 3; idx += 256) {
            int pr = idx / (PC * 3);
            int rem = idx - pr * (PC * 3);
            int pc = rem / 3, c = rem - pc * 3;
            int h = g0r + pr; if (h < 0) h += Hin; if (h >= Hin) h -= Hin;
            int w = g0c + pc; if (w < 0) w += Hin; if (w >= Hin) w -= Hin;
            s_in[(slot * 3 + c) * CS + pr * PC + pc] = ib[(h * Hin + w) * 3 + c];
        }
    }
    __syncthreads();

    // ---- Row pass (m = slot) ----
#pragma unroll
    for (int m = 0; m < 2; m++) {
        u64 f2[10];
#pragma unroll
        for (int u = 0; u < 10; u++)
            f2[u] = pk(c_filt[40 + (m * 2 + 0) * 10 + 9 - u],
                       c_filt[40 + (m * 2 + 1) * 10 + 9 - u]);
        for (int idx = tid; idx < TI * 3 * PC; idx += 256) {
            int pc = idx % PC;
            int t = idx / PC;
            int c = t % 3, i = t / 3;
            const float* pin = s_in + (m * 3 + c) * CS + (2 * i) * PC + pc;
            u64 acc = 0;
#pragma unroll
            for (int u = 0; u < 10; u++) {
                float xv = pin[u * PC];
                acc = fma2(pk(xv, xv), f2[u], acc);
            }
            s_row[((m * TI + i) * PC + pc) * 3 + c] = acc;
        }
    }
    __syncthreads();

    // ---- Col pass + pair combine ----
    for (int idx = tid; idx < TI * TJ * 3; idx += 256) {
        int c = idx % 3;
        int t = idx / 3;
        int j = t % TJ, i = t / TJ;
        float ll[2], vs[3][2];
#pragma unroll
        for (int slot = 0; slot < 2; slot++) {
            const int n = slot ^ p;
            const u64* R = s_row + ((slot * TI + i) * PC + 2 * j) * 3 + c;
            u64 A = 0, B = 0;
#pragma unroll
            for (int u = 0; u < 10; u++) {
                u64 wv = R[u * 3];
                float fl = c_filt[40 + (n * 2 + 0) * 10 + 9 - u];
                float fh = c_filt[40 + (n * 2 + 1) * 10 + 9 - u];
                A = fma2(pk(fl, fl), wv, A);
                B = fma2(pk(fh, fh), wv, B);
            }
            unpk(A, ll[slot], vs[1][slot]);
            unpk(B, vs[0][slot], vs[2][slot]);
        }
        const int oi = i0 + i, oj = j0 + j;
        float* ob = out + b * (1024 * 1024 * 3);
        if (FINAL) {
#pragma unroll
            for (int slot = 0; slot < 2; slot++) {
                int tr = slot == 0 ? p : 3 - p;
                int m = tr >> 1, n = tr & 1;
                ob[((m * 512 + oi) * 1024 + n * 512 + oj) * 3 + c] = ll[slot];
            }
        } else {
#pragma unroll
            for (int slot = 0; slot < 2; slot++) {
                int tr = slot == 0 ? p : 3 - p;
                lo_out[((tr * 8 + b) * (Hout * Hout) + oi * Hout + oj) * 3 + c] = ll[slot];
            }
        }
#pragma unroll
        for (int s = 0; s < 3; s++) {
            const int ro = (s == 0) ? 0 : SBS;
            const int co = (s == 1) ? 0 : SBS;
            float sum = (vs[s][0] + vs[s][1]) * INV_SQRT2;
            float dif = (vs[s][0] - vs[s][1]) * INV_SQRT2;
            int r = ro + oi, cc = co + oj;
            ob[(r * 1024 + p * 512 + cc) * 3 + c] = sum;              // tile (0,p)
            ob[((512 + r) * 1024 + (1 - p) * 512 + cc) * 3 + c] = dif; // tile (1,1-p)
        }
    }
}

extern "C" void kernel_launch(void* const* d_in, const int* in_sizes, int n_in,
                              void* d_out, int out_size)
{
    const float* x   = (const float*)d_in[0];
    const float* Faf = (const float*)d_in[1];
    const float* af  = (const float*)d_in[2];
    float* out = (float*)d_out;

    float *lo1, *lo2;
    cudaGetSymbolAddress((void**)&lo1, g_lo1);
    cudaGetSymbolAddress((void**)&lo2, g_lo2);

    cudaMemcpyToSymbolAsync(c_filt, Faf, 40 * sizeof(float), 0,
                            cudaMemcpyDeviceToDevice);
    cudaMemcpyToSymbolAsync(c_filt, af, 40 * sizeof(float), 40 * sizeof(float),
                            cudaMemcpyDeviceToDevice);

    // Level 1: x (512) -> subbands(256) + lo1(256)
    {
        constexpr int TI = 8, TJ = 16;
        constexpr int CS = (2 * TI + 8) * (2 * TJ + 8) + 8;       // 968
        dim3 grid((256 / TI) * (256 / TJ), 8);                    // 512 x 8
        size_t smem = 3 * CS * 4 + 2 * TI * (2 * TJ + 8) * 3 * 8; // 26976 B
        afb_l1<TI, TJ><<<grid, 256, smem>>>(x, lo1, out);
    }
    // Level 2: lo1 (256) -> subbands(128) + lo2(128)
    {
        constexpr int TI = 8, TJ = 16, H = 256;
        constexpr int CS = (2 * TI + 8) * (2 * TJ + 8) + 8;       // 968
        dim3 grid((H / 2 / TI) * (H / 2 / TJ), 2, 8);             // 128 x 2 x 8
        size_t smem = 6 * CS * 4 + 2 * TI * (2 * TJ + 8) * 3 * 8; // 38592 B
        afb_l23<TI, TJ, H, 128, false><<<grid, 256, smem>>>(lo1, lo2, out);
    }
    // Level 3: lo2 (128) -> subbands(64) + raw lowpass
    {
        constexpr int TI = 8, TJ = 8, H = 128;
        constexpr int CS = (2 * TI + 8) * (2 * TJ + 8) + 8;       // 584
        dim3 grid((H / 2 / TI) * (H / 2 / TJ), 2, 8);             // 64 x 2 x 8
        size_t smem = 6 * CS * 4 + 2 * TI * (2 * TJ + 8) * 3 * 8; // 23232 B
        afb_l23<TI, TJ, H, 64, true><<<grid, 256, smem>>>(lo2, nullptr, out);
    }
}

// round 4
// speedup vs baseline: 1.3915x; 1.0993x over previous
#include <cuda_runtime.h>

#define INV_SQRT2 0.70710678118654752440f

// Inter-level lowpass scratch, layout [tree][b][h][w][c] (c fastest)
__device__ float g_lo1[4 * 8 * 256 * 256 * 3];
__device__ float g_lo2[4 * 8 * 128 * 128 * 3];

// ---- Filter taps as compile-time constants (Farras + Kingsbury Q-shift) ----
#define C_F ((float)0.08838834764832)
#define C_G ((float)0.01122679215254)
#define C_H ((float)0.69587998903400)
#define C_A ((float)0.03516384)
#define C_B ((float)0.08832942)
#define C_C ((float)0.23389032)
#define C_D ((float)0.76027237)
#define C_E ((float)0.58751830)
#define C_K ((float)0.11430184)

__device__ __forceinline__ constexpr float FTAP(int m, int lh, int u) {
    constexpr float T[2][2][10] = {
        {{0.f, -C_F, C_F, C_H, C_H, C_F, -C_F, C_G, C_G, 0.f},
         {0.f, -C_G, C_G, C_F, C_F, -C_H, C_H, -C_F, -C_F, 0.f}},
        {{C_G, C_G, -C_F, C_F, C_H, C_H, C_F, -C_F, 0.f, 0.f},
         {0.f, 0.f, -C_F, -C_F, C_H, -C_H, C_F, C_F, C_G, -C_G}}};
    return T[m][lh][u];
}
__device__ __forceinline__ constexpr float DTAP(int m, int lh, int u) {
    constexpr float T[2][2][10] = {
        {{C_A, 0.f, -C_B, C_C, C_D, C_E, 0.f, -C_K, 0.f, 0.f},
         {0.f, 0.f, -C_K, 0.f, C_E, -C_D, C_C, C_B, 0.f, -C_A}},
        {{0.f, 0.f, -C_K, 0.f, C_E, C_D, C_C, -C_B, 0.f, C_A},
         {-C_A, 0.f, C_B, C_C, -C_D, C_E, 0.f, -C_K, 0.f, 0.f}}};
    return T[m][lh][u];
}
__device__ __forceinline__ constexpr float TAP(int bank, int m, int lh, int u) {
    return bank ? DTAP(m, lh, u) : FTAP(m, lh, u);
}

// ---- Row (vertical) conv: 4 pc positions, lo+hi filters, immediates ----
template <int BANK, int M, int PC>
__device__ __forceinline__ void rowconv(const float* pin, float4& lo, float4& hi) {
    lo = make_float4(0.f, 0.f, 0.f, 0.f);
    hi = make_float4(0.f, 0.f, 0.f, 0.f);
#pragma unroll
    for (int u = 0; u < 10; u++) {
        const float L = TAP(BANK, M, 0, 9 - u);
        const float H = TAP(BANK, M, 1, 9 - u);
        if (L != 0.f || H != 0.f) {
            float4 xv = *(const float4*)(pin + u * PC);
            if (L != 0.f) { lo.x += L * xv.x; lo.y += L * xv.y; lo.z += L * xv.z; lo.w += L * xv.w; }
            if (H != 0.f) { hi.x += H * xv.x; hi.y += H * xv.y; hi.z += H * xv.z; hi.w += H * xv.w; }
        }
    }
}

// Row pass over the block tile for one (bank, m/slot).
template <int BANK, int M, int TI, int PC, int CS, int SRS>
__device__ __forceinline__ void row_pass(const float* s_in, float* s_row, int tid) {
    constexpr int PCQ = PC / 4;
    for (int idx = tid; idx < TI * 3 * PCQ; idx += 256) {
        int q = idx % PCQ;
        int t = idx / PCQ;
        int c = t % 3, i = t / 3;
        const float* pin = s_in + c * CS + (2 * i) * PC + q * 4;
        float4 lo, hi;
        rowconv<BANK, M, PC>(pin, lo, hi);
        *(float4*)(s_row + ((M * 2 + 0) * 3 + c) * SRS + i * PC + q * 4) = lo;
        *(float4*)(s_row + ((M * 2 + 1) * 3 + c) * SRS + i * PC + q * 4) = hi;
    }
}

// Load a 12-float window (3x LDS.128) from a s_row plane.
template <int PC, int SRS>
__device__ __forceinline__ void load12(const float* s_row, int plane, int i, int jp, float* r) {
    const float* p = s_row + plane * SRS + i * PC + 4 * jp;
#pragma unroll
    for (int q = 0; q < 3; q++) {
        float4 v = *(const float4*)(p + 4 * q);
        r[4 * q] = v.x; r[4 * q + 1] = v.y; r[4 * q + 2] = v.z; r[4 * q + 3] = v.w;
    }
}

// Column (horizontal) conv: 2 adjacent j outputs from a 12-window, lo+hi.
template <int BANK, int N>
__device__ __forceinline__ void colconv(const float r[12], float lo[2], float hi[2]) {
    lo[0] = lo[1] = hi[0] = hi[1] = 0.f;
#pragma unroll
    for (int u = 0; u < 10; u++) {
        const float L = TAP(BANK, N, 0, 9 - u);
        const float H = TAP(BANK, N, 1, 9 - u);
#pragma unroll
        for (int p = 0; p < 2; p++) {
            float xv = r[2 * p + u];
            if (L != 0.f) lo[p] += L * xv;
            if (H != 0.f) hi[p] += H * xv;
        }
    }
}

// =============================== Level 1 ===================================
template <int TI, int TJ>
__global__ __launch_bounds__(256, 4) void afb_l1(
    const float* __restrict__ x, float* __restrict__ lo1, float* __restrict__ out)
{
    constexpr int PR = 2 * TI + 8, PC = 2 * TJ + 8, JP = TJ / 2;
    constexpr int CS = PR * PC + 4;
    constexpr int SRS = TI * PC + 4;
    extern __shared__ float sm[];
    float* s_in = sm;               // [c][PR][PC], 3*CS
    float* s_row = sm + 3 * CS;     // [(m*2+lh)*3+c][TI][PC], 12*SRS

    const int tid = threadIdx.x, b = blockIdx.y;
    constexpr int TW = 256 / TJ;
    const int i0 = (blockIdx.x / TW) * TI, j0 = (blockIdx.x % TW) * TJ;
    const int g0r = 2 * i0 - 4, g0c = 2 * j0 - 4;
    const float* xb = x + b * (512 * 512 * 3);

    for (int idx = tid; idx < PR * PC * 3; idx += 256) {
        int pr = idx / (PC * 3);
        int rem = idx - pr * (PC * 3);
        int pc = rem / 3, c = rem - pc * 3;
        int h = g0r + pr; if (h < 0) h += 512; if (h >= 512) h -= 512;
        int w = g0c + pc; if (w < 0) w += 512; if (w >= 512) w -= 512;
        s_in[c * CS + pr * PC + pc] = xb[(h * 512 + w) * 3 + c] * 0.5f;
    }
    __syncthreads();

    row_pass<0, 0, TI, PC, CS, SRS>(s_in, s_row, tid);
    row_pass<0, 1, TI, PC, CS, SRS>(s_in, s_row, tid);
    __syncthreads();

    float* ob = out + b * (1024 * 1024 * 3);
    for (int idx = tid; idx < TI * JP * 3; idx += 256) {
        int c = idx % 3;
        int t = idx / 3;
        int jp = t % JP, i = t / JP;
        const int oi = i0 + i, oj = j0 + 2 * jp;

        float r0[12], r1[12];
        float ll0[2], lh0[2], ll1[2], lh1[2], ll2[2], lh2[2], ll3[2], lh3[2];
        // rowlo windows (m=0 plane c, m=1 plane 6+c)
        load12<PC, SRS>(s_row, 0 + c, i, jp, r0);
        load12<PC, SRS>(s_row, 6 + c, i, jp, r1);
        colconv<0, 0>(r0, ll0, lh0);   // tree (0,0)
        colconv<0, 1>(r0, ll1, lh1);   // tree (0,1)
        colconv<0, 0>(r1, ll2, lh2);   // tree (1,0)
        colconv<0, 1>(r1, ll3, lh3);   // tree (1,1)

        // lowpass -> lo1 [tree][b][h][w][c]
        {
            int base = (b * 65536 + oi * 256 + oj) * 3 + c;
            constexpr int TS = 8 * 65536 * 3;
            lo1[base]               = ll0[0]; lo1[base + 3]               = ll0[1];
            lo1[base + TS]          = ll1[0]; lo1[base + TS + 3]          = ll1[1];
            lo1[base + 2 * TS]      = ll2[0]; lo1[base + 2 * TS + 3]      = ll2[1];
            lo1[base + 3 * TS]      = ll3[0]; lo1[base + 3 * TS + 3]      = ll3[1];
        }
        // subband s=0 (LH) at (0,256)
#pragma unroll
        for (int p = 0; p < 2; p++) {
            float p00 = (lh0[p] + lh3[p]) * INV_SQRT2;
            float p11 = (lh0[p] - lh3[p]) * INV_SQRT2;
            float p01 = (lh1[p] + lh2[p]) * INV_SQRT2;
            float p10 = (lh1[p] - lh2[p]) * INV_SQRT2;
            int r = oi, cc = 256 + oj + p;
            ob[(r * 1024 + cc) * 3 + c] = p00;
            ob[(r * 1024 + 512 + cc) * 3 + c] = p01;
            ob[((512 + r) * 1024 + cc) * 3 + c] = p10;
            ob[((512 + r) * 1024 + 512 + cc) * 3 + c] = p11;
        }
        // rowhi windows -> HL (256,0) and HH (256,256)
        load12<PC, SRS>(s_row, 3 + c, i, jp, r0);
        load12<PC, SRS>(s_row, 9 + c, i, jp, r1);
        colconv<0, 0>(r0, ll0, lh0);
        colconv<0, 1>(r0, ll1, lh1);
        colconv<0, 0>(r1, ll2, lh2);
        colconv<0, 1>(r1, ll3, lh3);
#pragma unroll
        for (int s = 1; s < 3; s++) {
            const int ro = 256;
            const int co = (s == 1) ? 0 : 256;
#pragma unroll
            for (int p = 0; p < 2; p++) {
                float a0 = (s == 1) ? ll0[p] : lh0[p];
                float a1 = (s == 1) ? ll1[p] : lh1[p];
                float a2 = (s == 1) ? ll2[p] : lh2[p];
                float a3 = (s == 1) ? ll3[p] : lh3[p];
                float p00 = (a0 + a3) * INV_SQRT2;
                float p11 = (a0 - a3) * INV_SQRT2;
                float p01 = (a1 + a2) * INV_SQRT2;
                float p10 = (a1 - a2) * INV_SQRT2;
                int r = ro + oi, cc = co + oj + p;
                ob[(r * 1024 + cc) * 3 + c] = p00;
                ob[(r * 1024 + 512 + cc) * 3 + c] = p01;
                ob[((512 + r) * 1024 + cc) * 3 + c] = p10;
                ob[((512 + r) * 1024 + 512 + cc) * 3 + c] = p11;
            }
        }
    }
}

// ============================ Levels 2 and 3 ===============================
// Pair P: slot0 = tree P (row m=0, col n=P), slot1 = tree 3-P (m=1, n=1-P).
template <int P, int TI, int TJ, int Hin, int SBS, bool FINAL>
__global__ __launch_bounds__(256, 4) void afb_l23(
    const float* __restrict__ lo_in, float* __restrict__ lo_out,
    float* __restrict__ out)
{
    constexpr int PR = 2 * TI + 8, PC = 2 * TJ + 8, JP = TJ / 2;
    constexpr int CS = PR * PC + 4;
    constexpr int SRS = TI * PC + 4;
    constexpr int Hout = Hin / 2;
    extern __shared__ float sm[];
    float* s_in = sm;               // [slot*3+c][PR][PC], 6*CS
    float* s_row = sm + 6 * CS;     // 12*SRS

    const int tid = threadIdx.x, b = blockIdx.y;
    constexpr int TW = Hout / TJ;
    const int i0 = (blockIdx.x / TW) * TI, j0 = (blockIdx.x % TW) * TJ;
    const int g0r = 2 * i0 - 4, g0c = 2 * j0 - 4;

#pragma unroll
    for (int slot = 0; slot < 2; slot++) {
        const int tr = slot ? (3 - P) : P;
        const float* ib = lo_in + (tr * 8 + b) * (Hin * Hin * 3);
        for (int idx = tid; idx < PR * PC * 3; idx += 256) {
            int pr = idx / (PC * 3);
            int rem = idx - pr * (PC * 3);
            int pc = rem / 3, c = rem - pc * 3;
            int h = g0r + pr; if (h < 0) h += Hin; if (h >= Hin) h -= Hin;
            int w = g0c + pc; if (w < 0) w += Hin; if (w >= Hin) w -= Hin;
            s_in[(slot * 3 + c) * CS + pr * PC + pc] = ib[(h * Hin + w) * 3 + c];
        }
    }
    __syncthreads();

    row_pass<1, 0, TI, PC, CS, SRS>(s_in, s_row, tid);            // slot0
    row_pass<1, 1, TI, PC, CS, SRS>(s_in + 3 * CS, s_row, tid);   // slot1
    __syncthreads();

    constexpr int N0 = P, N1 = 1 - P;
    float* ob = out + b * (1024 * 1024 * 3);
    for (int idx = tid; idx < TI * JP * 3; idx += 256) {
        int c = idx % 3;
        int t = idx / 3;
        int jp = t % JP, i = t / JP;
        const int oi = i0 + i, oj = j0 + 2 * jp;

        float r0[12], r1[12];
        float llA[2], lhA[2], llB[2], lhB[2];
        load12<PC, SRS>(s_row, 0 + c, i, jp, r0);   // slot0 rowlo
        load12<PC, SRS>(s_row, 6 + c, i, jp, r1);   // slot1 rowlo
        colconv<1, N0>(r0, llA, lhA);
        colconv<1, N1>(r1, llB, lhB);

        if (FINAL) {
            constexpr int nA = P & 1, nB = 1 - P;   // mA=0, mB=1
#pragma unroll
            for (int p = 0; p < 2; p++) {
                ob[((oi) * 1024 + nA * 512 + oj + p) * 3 + c] = llA[p];
                ob[((512 + oi) * 1024 + nB * 512 + oj + p) * 3 + c] = llB[p];
            }
        } else {
            int baseA = ((P * 8 + b) * (Hout * Hout) + oi * Hout + oj) * 3 + c;
            lo_out[baseA] = llA[0]; lo_out[baseA + 3] = llA[1];
            int baseB = (((3 - P) * 8 + b) * (Hout * Hout) + oi * Hout + oj) * 3 + c;
            lo_out[baseB] = llB[0]; lo_out[baseB + 3] = llB[1];
        }
        // s=0 (LH) @ (0, SBS)
#pragma unroll
        for (int p = 0; p < 2; p++) {
            float s_ = (lhA[p] + lhB[p]) * INV_SQRT2;
            float d_ = (lhA[p] - lhB[p]) * INV_SQRT2;
            int r = oi, cc = SBS + oj + p;
            ob[(r * 1024 + P * 512 + cc) * 3 + c] = s_;
            ob[((512 + r) * 1024 + (1 - P) * 512 + cc) * 3 + c] = d_;
        }
        // rowhi -> s=1 (HL) @ (SBS,0), s=2 (HH) @ (SBS,SBS)
        load12<PC, SRS>(s_row, 3 + c, i, jp, r0);
        load12<PC, SRS>(s_row, 9 + c, i, jp, r1);
        colconv<1, N0>(r0, llA, lhA);
        colconv<1, N1>(r1, llB, lhB);
#pragma unroll
        for (int p = 0; p < 2; p++) {
            float s1 = (llA[p] + llB[p]) * INV_SQRT2;
            float d1 = (llA[p] - llB[p]) * INV_SQRT2;
            float s2 = (lhA[p] + lhB[p]) * INV_SQRT2;
            float d2 = (lhA[p] - lhB[p]) * INV_SQRT2;
            int r = SBS + oi;
            ob[(r * 1024 + P * 512 + oj + p) * 3 + c] = s1;
            ob[((512 + r) * 1024 + (1 - P) * 512 + oj + p) * 3 + c] = d1;
            int cc = SBS + oj + p;
            ob[(r * 1024 + P * 512 + cc) * 3 + c] = s2;
            ob[((512 + r) * 1024 + (1 - P) * 512 + cc) * 3 + c] = d2;
        }
    }
}

extern "C" void kernel_launch(void* const* d_in, const int* in_sizes, int n_in,
                              void* d_out, int out_size)
{
    const float* x = (const float*)d_in[0];
    float* out = (float*)d_out;

    float *lo1, *lo2;
    cudaGetSymbolAddress((void**)&lo1, g_lo1);
    cudaGetSymbolAddress((void**)&lo2, g_lo2);

    // Level 1: x (512) -> subbands(256) + lo1(256)
    {
        constexpr int TI = 8, TJ = 16;
        constexpr int CS = (2 * TI + 8) * (2 * TJ + 8) + 4;   // 964
        constexpr int SRS = TI * (2 * TJ + 8) + 4;            // 324
        dim3 grid((256 / TI) * (256 / TJ), 8);                // 512 x 8
        size_t smem = (3 * CS + 12 * SRS) * sizeof(float);    // 27120 B
        afb_l1<TI, TJ><<<grid, 256, smem>>>(x, lo1, out);
    }
    // Level 2: lo1 (256) -> subbands(128) + lo2(128), pairs P=0,1
    {
        constexpr int TI = 8, TJ = 16, H = 256;
        constexpr int CS = (2 * TI + 8) * (2 * TJ + 8) + 4;
        constexpr int SRS = TI * (2 * TJ + 8) + 4;
        dim3 grid((128 / TI) * (128 / TJ), 8);                // 128 x 8
        size_t smem = (6 * CS + 12 * SRS) * sizeof(float);    // 38688 B
        afb_l23<0, TI, TJ, H, 128, false><<<grid, 256, smem>>>(lo1, lo2, out);
        afb_l23<1, TI, TJ, H, 128, false><<<grid, 256, smem>>>(lo1, lo2, out);
    }
    // Level 3: lo2 (128) -> subbands(64) + raw lowpass
    {
        constexpr int TI = 8, TJ = 16, H = 128;
        constexpr int CS = (2 * TI + 8) * (2 * TJ + 8) + 4;
        constexpr int SRS = TI * (2 * TJ + 8) + 4;
        dim3 grid((64 / TI) * (64 / TJ), 8);                  // 32 x 8
        size_t smem = (6 * CS + 12 * SRS) * sizeof(float);
        afb_l23<0, TI, TJ, H, 64, true><<<grid, 256, smem>>>(lo2, nullptr, out);
        afb_l23<1, TI, TJ, H, 64, true><<<grid, 256, smem>>>(lo2, nullptr, out);
    }
}

// round 5
// speedup vs baseline: 1.8248x; 1.3114x over previous
#include <cuda_runtime.h>

#define INV_SQRT2 0.70710678118654752440f

// Inter-level lowpass scratch, layout [tree][b][h][w][c] (c fastest)
__device__ float g_lo1[4 * 8 * 256 * 256 * 3];
__device__ float g_lo2[4 * 8 * 128 * 128 * 3];

// ---- Filter taps as compile-time constants (Farras + Kingsbury Q-shift) ----
#define C_F ((float)0.08838834764832)
#define C_G ((float)0.01122679215254)
#define C_H ((float)0.69587998903400)
#define C_A ((float)0.03516384)
#define C_B ((float)0.08832942)
#define C_C ((float)0.23389032)
#define C_D ((float)0.76027237)
#define C_E ((float)0.58751830)
#define C_K ((float)0.11430184)

__device__ __forceinline__ constexpr float FTAP(int m, int lh, int u) {
    constexpr float T[2][2][10] = {
        {{0.f, -C_F, C_F, C_H, C_H, C_F, -C_F, C_G, C_G, 0.f},
         {0.f, -C_G, C_G, C_F, C_F, -C_H, C_H, -C_F, -C_F, 0.f}},
        {{C_G, C_G, -C_F, C_F, C_H, C_H, C_F, -C_F, 0.f, 0.f},
         {0.f, 0.f, -C_F, -C_F, C_H, -C_H, C_F, C_F, C_G, -C_G}}};
    return T[m][lh][u];
}
__device__ __forceinline__ constexpr float DTAP(int m, int lh, int u) {
    constexpr float T[2][2][10] = {
        {{C_A, 0.f, -C_B, C_C, C_D, C_E, 0.f, -C_K, 0.f, 0.f},
         {0.f, 0.f, -C_K, 0.f, C_E, -C_D, C_C, C_B, 0.f, -C_A}},
        {{0.f, 0.f, -C_K, 0.f, C_E, C_D, C_C, -C_B, 0.f, C_A},
         {-C_A, 0.f, C_B, C_C, -C_D, C_E, 0.f, -C_K, 0.f, 0.f}}};
    return T[m][lh][u];
}
__device__ __forceinline__ constexpr float TAP(int bank, int m, int lh, int u) {
    return bank ? DTAP(m, lh, u) : FTAP(m, lh, u);
}

// ---- Paired-row streaming conv: output rows 2i2, 2i2+1, 4 cols, lo+hi ----
template <int BANK, int M, int PC>
__device__ __forceinline__ void rowconv_pair(
    const float* pin, float4& lo0, float4& hi0, float4& lo1, float4& hi1)
{
    lo0 = hi0 = lo1 = hi1 = make_float4(0.f, 0.f, 0.f, 0.f);
#pragma unroll
    for (int u = 0; u < 12; u++) {
        const float L0 = (u < 10) ? TAP(BANK, M, 0, 9 - u) : 0.f;
        const float H0 = (u < 10) ? TAP(BANK, M, 1, 9 - u) : 0.f;
        const float L1 = (u >= 2) ? TAP(BANK, M, 0, 11 - u) : 0.f;
        const float H1 = (u >= 2) ? TAP(BANK, M, 1, 11 - u) : 0.f;
        if (L0 != 0.f || H0 != 0.f || L1 != 0.f || H1 != 0.f) {
            float4 xv = *(const float4*)(pin + u * PC);
            if (L0 != 0.f) { lo0.x += L0 * xv.x; lo0.y += L0 * xv.y; lo0.z += L0 * xv.z; lo0.w += L0 * xv.w; }
            if (H0 != 0.f) { hi0.x += H0 * xv.x; hi0.y += H0 * xv.y; hi0.z += H0 * xv.z; hi0.w += H0 * xv.w; }
            if (L1 != 0.f) { lo1.x += L1 * xv.x; lo1.y += L1 * xv.y; lo1.z += L1 * xv.z; lo1.w += L1 * xv.w; }
            if (H1 != 0.f) { hi1.x += H1 * xv.x; hi1.y += H1 * xv.y; hi1.z += H1 * xv.z; hi1.w += H1 * xv.w; }
        }
    }
}

// Row pass: each task = (i2, c, q) -> rows 2i2, 2i2+1, cols 4q..4q+3.
template <int BANK, int M, int TI, int PC, int CS, int SRS>
__device__ __forceinline__ void row_pass(const float* s_in, float* s_row, int start) {
    constexpr int PCQ = PC / 4;
    constexpr int NT = (TI / 2) * 3 * PCQ;
    for (int idx = start; idx < NT; idx += 256) {
        int q = idx % PCQ;
        int t = idx / PCQ;
        int c = t % 3, i2 = t / 3;
        const float* pin = s_in + c * CS + (4 * i2) * PC + q * 4;
        float4 lo0, hi0, lo1, hi1;
        rowconv_pair<BANK, M, PC>(pin, lo0, hi0, lo1, hi1);
        float* plo = s_row + ((M * 2 + 0) * 3 + c) * SRS + (2 * i2) * PC + q * 4;
        float* phi = s_row + ((M * 2 + 1) * 3 + c) * SRS + (2 * i2) * PC + q * 4;
        *(float4*)plo = lo0; *(float4*)(plo + PC) = lo1;
        *(float4*)phi = hi0; *(float4*)(phi + PC) = hi1;
    }
}

// Load a 12-float window (3x LDS.128) from a s_row plane.
template <int PC, int SRS>
__device__ __forceinline__ void load12(const float* s_row, int plane, int i, int jp, float* r) {
    const float* p = s_row + plane * SRS + i * PC + 4 * jp;
#pragma unroll
    for (int q = 0; q < 3; q++) {
        float4 v = *(const float4*)(p + 4 * q);
        r[4 * q] = v.x; r[4 * q + 1] = v.y; r[4 * q + 2] = v.z; r[4 * q + 3] = v.w;
    }
}

// Column conv: 2 adjacent j outputs from a 12-window, lo+hi filters.
template <int BANK, int N>
__device__ __forceinline__ void colconv(const float r[12], float lo[2], float hi[2]) {
    lo[0] = lo[1] = hi[0] = hi[1] = 0.f;
#pragma unroll
    for (int u = 0; u < 10; u++) {
        const float L = TAP(BANK, N, 0, 9 - u);
        const float H = TAP(BANK, N, 1, 9 - u);
#pragma unroll
        for (int p = 0; p < 2; p++) {
            float xv = r[2 * p + u];
            if (L != 0.f) lo[p] += L * xv;
            if (H != 0.f) hi[p] += H * xv;
        }
    }
}

// =============================== Level 1 ===================================
template <int TI, int TJ>
__global__ __launch_bounds__(256, 4) void afb_l1(
    const float* __restrict__ x, float* __restrict__ lo1, float* __restrict__ out)
{
    constexpr int PR = 2 * TI + 8, PC = 2 * TJ + 8, JP = TJ / 2;
    constexpr int CS = PR * PC + 4;
    constexpr int SRS = TI * PC + 4;
    extern __shared__ float sm[];
    float* s_in = sm;               // [c][PR][PC]
    float* s_row = sm + 3 * CS;     // [(m*2+lh)*3+c][TI][PC]

    const int tid = threadIdx.x, b = blockIdx.y;
    constexpr int TW = 256 / TJ;
    const int i0 = (blockIdx.x / TW) * TI, j0 = (blockIdx.x % TW) * TJ;
    const int g0r = 2 * i0 - 4, g0c = 2 * j0 - 4;
    const float* xb = x + b * (512 * 512 * 3);

    for (int idx = tid; idx < PR * PC * 3; idx += 256) {
        int pr = idx / (PC * 3);
        int rem = idx - pr * (PC * 3);
        int pc = rem / 3, c = rem - pc * 3;
        int h = g0r + pr; if (h < 0) h += 512; if (h >= 512) h -= 512;
        int w = g0c + pc; if (w < 0) w += 512; if (w >= 512) w -= 512;
        s_in[c * CS + pr * PC + pc] = xb[(h * 512 + w) * 3 + c] * 0.5f;
    }
    __syncthreads();

    row_pass<0, 0, TI, PC, CS, SRS>(s_in, s_row, tid);
    row_pass<0, 1, TI, PC, CS, SRS>(s_in, s_row, tid);
    __syncthreads();

    // Col pass: tasks (set, i, jp, c); set0 = rowlo -> LL + LH, set1 = rowhi -> HL + HH.
    float* ob = out + b * (1024 * 1024 * 3);
    constexpr int NT = 2 * TI * JP * 3;
    for (int idx = tid; idx < NT; idx += 256) {
        int c = idx % 3;
        int t = idx / 3;
        int jp = t % JP; t /= JP;
        int i = t % TI;
        int set = t / TI;
        const int oi = i0 + i, oj = j0 + 2 * jp;

        float W0[12], W1[12];
        load12<PC, SRS>(s_row, (0 + set) * 3 + c, i, jp, W0);  // m=0, lh=set
        load12<PC, SRS>(s_row, (2 + set) * 3 + c, i, jp, W1);  // m=1, lh=set
        float a_lo[2], a_hi[2], b_lo[2], b_hi[2];
        float c_lo[2], c_hi[2], d_lo[2], d_hi[2];
        colconv<0, 0>(W0, a_lo, a_hi);   // tree (0,0)
        colconv<0, 1>(W0, b_lo, b_hi);   // tree (0,1)
        colconv<0, 0>(W1, c_lo, c_hi);   // tree (1,0)
        colconv<0, 1>(W1, d_lo, d_hi);   // tree (1,1)

        if (set == 0) {
            // lowpass -> lo1 [tree][b][h][w][c]
            int base = (b * 65536 + oi * 256 + oj) * 3 + c;
            constexpr int TS = 8 * 65536 * 3;
            lo1[base]              = a_lo[0]; lo1[base + 3]              = a_lo[1];
            lo1[base + TS]         = b_lo[0]; lo1[base + TS + 3]         = b_lo[1];
            lo1[base + 2 * TS]     = c_lo[0]; lo1[base + 2 * TS + 3]     = c_lo[1];
            lo1[base + 3 * TS]     = d_lo[0]; lo1[base + 3 * TS + 3]     = d_lo[1];
            // LH subband @ (0, 256)
#pragma unroll
            for (int p = 0; p < 2; p++) {
                float p00 = (a_hi[p] + d_hi[p]) * INV_SQRT2;
                float p11 = (a_hi[p] - d_hi[p]) * INV_SQRT2;
                float p01 = (b_hi[p] + c_hi[p]) * INV_SQRT2;
                float p10 = (b_hi[p] - c_hi[p]) * INV_SQRT2;
                int r = oi, cc = 256 + oj + p;
                ob[(r * 1024 + cc) * 3 + c] = p00;
                ob[(r * 1024 + 512 + cc) * 3 + c] = p01;
                ob[((512 + r) * 1024 + cc) * 3 + c] = p10;
                ob[((512 + r) * 1024 + 512 + cc) * 3 + c] = p11;
            }
        } else {
            // HL @ (256,0) from lo accs; HH @ (256,256) from hi accs
#pragma unroll
            for (int s = 0; s < 2; s++) {
#pragma unroll
                for (int p = 0; p < 2; p++) {
                    float a0 = s == 0 ? a_lo[p] : a_hi[p];
                    float a1 = s == 0 ? b_lo[p] : b_hi[p];
                    float a2 = s == 0 ? c_lo[p] : c_hi[p];
                    float a3 = s == 0 ? d_lo[p] : d_hi[p];
                    float p00 = (a0 + a3) * INV_SQRT2;
                    float p11 = (a0 - a3) * INV_SQRT2;
                    float p01 = (a1 + a2) * INV_SQRT2;
                    float p10 = (a1 - a2) * INV_SQRT2;
                    int r = 256 + oi, cc = (s == 0 ? 0 : 256) + oj + p;
                    ob[(r * 1024 + cc) * 3 + c] = p00;
                    ob[(r * 1024 + 512 + cc) * 3 + c] = p01;
                    ob[((512 + r) * 1024 + cc) * 3 + c] = p10;
                    ob[((512 + r) * 1024 + 512 + cc) * 3 + c] = p11;
                }
            }
        }
    }
}

// ============================ Levels 2 and 3 ===============================
// Pair P: slot0 = tree P (row m=0, col n=P), slot1 = tree 3-P (m=1, n=1-P).
template <int P, int TI, int TJ, int Hin, int SBS, bool FINAL>
__device__ __forceinline__ void l23_body(
    const float* __restrict__ lo_in, float* __restrict__ lo_out,
    float* __restrict__ out, int b, float* sm)
{
    constexpr int PR = 2 * TI + 8, PC = 2 * TJ + 8, JP = TJ / 2;
    constexpr int CS = PR * PC + 4;
    constexpr int SRS = TI * PC + 4;
    constexpr int Hout = Hin / 2;
    float* s_in = sm;               // [slot*3+c][PR][PC]
    float* s_row = sm + 6 * CS;     // [(slot*2+lh)*3+c][TI][PC]

    const int tid = threadIdx.x;
    constexpr int TW = Hout / TJ;
    const int i0 = (blockIdx.x / TW) * TI, j0 = (blockIdx.x % TW) * TJ;
    const int g0r = 2 * i0 - 4, g0c = 2 * j0 - 4;

#pragma unroll
    for (int slot = 0; slot < 2; slot++) {
        const int tr = slot ? (3 - P) : P;
        const float* ib = lo_in + (tr * 8 + b) * (Hin * Hin * 3);
        for (int idx = tid; idx < PR * PC * 3; idx += 256) {
            int pr = idx / (PC * 3);
            int rem = idx - pr * (PC * 3);
            int pc = rem / 3, c = rem - pc * 3;
            int h = g0r + pr; if (h < 0) h += Hin; if (h >= Hin) h -= Hin;
            int w = g0c + pc; if (w < 0) w += Hin; if (w >= Hin) w -= Hin;
            s_in[(slot * 3 + c) * CS + pr * PC + pc] = ib[(h * Hin + w) * 3 + c];
        }
    }
    __syncthreads();

    constexpr int RNT = (TI / 2) * 3 * (PC / 4);
    if (tid < RNT)            row_pass<1, 0, TI, PC, CS, SRS>(s_in, s_row, tid);
    else if (tid < 2 * RNT)   row_pass<1, 1, TI, PC, CS, SRS>(s_in + 3 * CS, s_row, tid - RNT);
    __syncthreads();

    constexpr int N0 = P, N1 = 1 - P;
    float* ob = out + b * (1024 * 1024 * 3);
    constexpr int NT = 2 * TI * JP * 3;
    for (int idx = tid; idx < NT; idx += 256) {
        int c = idx % 3;
        int t = idx / 3;
        int jp = t % JP; t /= JP;
        int i = t % TI;
        int set = t / TI;
        const int oi = i0 + i, oj = j0 + 2 * jp;

        float W0[12], W1[12];
        load12<PC, SRS>(s_row, (0 + set) * 3 + c, i, jp, W0);  // slot0, lh=set
        load12<PC, SRS>(s_row, (2 + set) * 3 + c, i, jp, W1);  // slot1, lh=set
        float A_lo[2], A_hi[2], B_lo[2], B_hi[2];
        colconv<1, N0>(W0, A_lo, A_hi);
        colconv<1, N1>(W1, B_lo, B_hi);

        if (set == 0) {
            if (FINAL) {
#pragma unroll
                for (int p = 0; p < 2; p++) {
                    ob[(oi * 1024 + P * 512 + oj + p) * 3 + c] = A_lo[p];
                    ob[((512 + oi) * 1024 + (1 - P) * 512 + oj + p) * 3 + c] = B_lo[p];
                }
            } else {
                int baseA = ((P * 8 + b) * (Hout * Hout) + oi * Hout + oj) * 3 + c;
                lo_out[baseA] = A_lo[0]; lo_out[baseA + 3] = A_lo[1];
                int baseB = (((3 - P) * 8 + b) * (Hout * Hout) + oi * Hout + oj) * 3 + c;
                lo_out[baseB] = B_lo[0]; lo_out[baseB + 3] = B_lo[1];
            }
            // LH @ (0, SBS)
#pragma unroll
            for (int p = 0; p < 2; p++) {
                float s_ = (A_hi[p] + B_hi[p]) * INV_SQRT2;
                float d_ = (A_hi[p] - B_hi[p]) * INV_SQRT2;
                int r = oi, cc = SBS + oj + p;
                ob[(r * 1024 + P * 512 + cc) * 3 + c] = s_;
                ob[((512 + r) * 1024 + (1 - P) * 512 + cc) * 3 + c] = d_;
            }
        } else {
            // HL @ (SBS,0), HH @ (SBS,SBS)
#pragma unroll
            for (int p = 0; p < 2; p++) {
                float s1 = (A_lo[p] + B_lo[p]) * INV_SQRT2;
                float d1 = (A_lo[p] - B_lo[p]) * INV_SQRT2;
                float s2 = (A_hi[p] + B_hi[p]) * INV_SQRT2;
                float d2 = (A_hi[p] - B_hi[p]) * INV_SQRT2;
                int r = SBS + oi;
                ob[(r * 1024 + P * 512 + oj + p) * 3 + c] = s1;
                ob[((512 + r) * 1024 + (1 - P) * 512 + oj + p) * 3 + c] = d1;
                int cc = SBS + oj + p;
                ob[(r * 1024 + P * 512 + cc) * 3 + c] = s2;
                ob[((512 + r) * 1024 + (1 - P) * 512 + cc) * 3 + c] = d2;
            }
        }
    }
}

template <int TI, int TJ, int Hin, int SBS, bool FINAL>
__global__ __launch_bounds__(256, 4) void afb_l23(
    const float* __restrict__ lo_in, float* __restrict__ lo_out,
    float* __restrict__ out)
{
    extern __shared__ float sm[];
    const int p = blockIdx.y >> 3, b = blockIdx.y & 7;
    if (p == 0) l23_body<0, TI, TJ, Hin, SBS, FINAL>(lo_in, lo_out, out, b, sm);
    else        l23_body<1, TI, TJ, Hin, SBS, FINAL>(lo_in, lo_out, out, b, sm);
}

extern "C" void kernel_launch(void* const* d_in, const int* in_sizes, int n_in,
                              void* d_out, int out_size)
{
    const float* x = (const float*)d_in[0];
    float* out = (float*)d_out;

    float *lo1, *lo2;
    cudaGetSymbolAddress((void**)&lo1, g_lo1);
    cudaGetSymbolAddress((void**)&lo2, g_lo2);

    // Level 1: x (512) -> subbands(256) + lo1(256)
    {
        constexpr int TI = 8, TJ = 32;
        constexpr int CS = (2 * TI + 8) * (2 * TJ + 8) + 4;   // 1732
        constexpr int SRS = TI * (2 * TJ + 8) + 4;            // 580
        dim3 grid((256 / TI) * (256 / TJ), 8);                // 256 x 8
        size_t smem = (3 * CS + 12 * SRS) * sizeof(float);    // 48624 B
        afb_l1<TI, TJ><<<grid, 256, smem>>>(x, lo1, out);
    }
    // Level 2: lo1 (256) -> subbands(128) + lo2(128), both pairs in one launch
    {
        constexpr int TI = 8, TJ = 16, H = 256;
        constexpr int CS = (2 * TI + 8) * (2 * TJ + 8) + 4;
        constexpr int SRS = TI * (2 * TJ + 8) + 4;
        dim3 grid((128 / TI) * (128 / TJ), 16);               // 128 x 16
        size_t smem = (6 * CS + 12 * SRS) * sizeof(float);    // 38688 B
        afb_l23<TI, TJ, H, 128, false><<<grid, 256, smem>>>(lo1, lo2, out);
    }
    // Level 3: lo2 (128) -> subbands(64) + raw lowpass, both pairs in one launch
    {
        constexpr int TI = 8, TJ = 16, H = 128;
        constexpr int CS = (2 * TI + 8) * (2 * TJ + 8) + 4;
        constexpr int SRS = TI * (2 * TJ + 8) + 4;
        dim3 grid((64 / TI) * (64 / TJ), 16);                 // 32 x 16
        size_t smem = (6 * CS + 12 * SRS) * sizeof(float);
        afb_l23<TI, TJ, H, 64, true><<<grid, 256, smem>>>(lo2, nullptr, out);
    }
}